// round 9
// baseline (speedup 1.0000x reference)
#include <cuda_runtime.h>
#include <cstdint>

#define BB 16
#define TT 2048
#define DD 1024
#define HH 64

// Scratch: q/k/v projections [B*T, H] fp32, and K-major tf32 weights.
__device__ float g_q[BB * TT * HH];
__device__ float g_k[BB * TT * HH];
__device__ float g_v[BB * TT * HH];
__device__ float g_wt[3 * HH * DD];   // Wt[(m*64+n)][k] = tf32(W_m[k][n]), K-major

__device__ __forceinline__ uint32_t f32_to_tf32(float f) {
    uint32_t u;
    asm("cvt.rna.tf32.f32 %0, %1;" : "=r"(u) : "f"(f));
    return u;
}

__device__ __forceinline__ void mma_tf32(float d[4], const uint32_t a[4],
                                         const uint32_t b[2]) {
    asm volatile(
        "mma.sync.aligned.m16n8k8.row.col.f32.tf32.tf32.f32 "
        "{%0,%1,%2,%3}, {%4,%5,%6,%7}, {%8,%9}, {%0,%1,%2,%3};"
        : "+f"(d[0]), "+f"(d[1]), "+f"(d[2]), "+f"(d[3])
        : "r"(a[0]), "r"(a[1]), "r"(a[2]), "r"(a[3]), "r"(b[0]), "r"(b[1]));
}

// ===========================================================================
// Kernel 0: W -> Wt[(m*64+n)][k], tf32-rounded, K-major.
// ===========================================================================
__global__ void wt_kernel(const float* __restrict__ Wq,
                          const float* __restrict__ Wk,
                          const float* __restrict__ Wv)
{
    const int idx = blockIdx.x * 256 + threadIdx.x;
    const int m = idx >> 16;
    const int n = (idx >> 10) & 63;
    const int k = idx & 1023;
    const float* W = (m == 0) ? Wq : (m == 1) ? Wk : Wv;
    ((uint32_t*)g_wt)[idx] = f32_to_tf32(W[k * HH + n]);
}

// ===========================================================================
// Kernel 1: tf32 mma.sync projection (unchanged, ~76us).
// ===========================================================================
#define AST 36
__global__ __launch_bounds__(256) void proj_mma_kernel(const float* __restrict__ x)
{
    __shared__ float As[128 * AST];
    __shared__ float Bs[192 * AST];

    const int tid  = threadIdx.x;
    const int warp = tid >> 5;
    const int lane = tid & 31;
    const int wr   = warp >> 2;
    const int wc   = warp & 3;
    const int row0 = blockIdx.x * 128;

    float d[4][6][4];
#pragma unroll
    for (int mt = 0; mt < 4; mt++)
#pragma unroll
        for (int nt = 0; nt < 6; nt++)
#pragma unroll
            for (int r = 0; r < 4; r++) d[mt][nt][r] = 0.f;

    float4 aP[4];
    uint4  bP[6];

#pragma unroll
    for (int t = 0; t < 4; t++) {
        const int idx = tid + t * 256;
        const int r  = idx >> 3, c4 = (idx & 7) * 4;
        aP[t] = *(const float4*)&x[(size_t)(row0 + r) * DD + c4];
    }
#pragma unroll
    for (int t = 0; t < 6; t++) {
        const int idx = tid + t * 256;
        const int n = idx >> 3, c4 = (idx & 7) * 4;
        bP[t] = *(const uint4*)&g_wt[n * DD + c4];
    }

#pragma unroll 1
    for (int chunk = 0; chunk < 32; chunk++) {
#pragma unroll
        for (int t = 0; t < 4; t++) {
            const int idx = tid + t * 256;
            const int r  = idx >> 3, c4 = (idx & 7) * 4;
            uint4 u;
            u.x = f32_to_tf32(aP[t].x); u.y = f32_to_tf32(aP[t].y);
            u.z = f32_to_tf32(aP[t].z); u.w = f32_to_tf32(aP[t].w);
            *(uint4*)&As[r * AST + c4] = u;
        }
#pragma unroll
        for (int t = 0; t < 6; t++) {
            const int idx = tid + t * 256;
            const int n = idx >> 3, c4 = (idx & 7) * 4;
            *(uint4*)&Bs[n * AST + c4] = bP[t];
        }
        __syncthreads();

        if (chunk < 31) {
            const int kc = (chunk + 1) * 32;
#pragma unroll
            for (int t = 0; t < 4; t++) {
                const int idx = tid + t * 256;
                const int r  = idx >> 3, c4 = (idx & 7) * 4;
                aP[t] = *(const float4*)&x[(size_t)(row0 + r) * DD + kc + c4];
            }
#pragma unroll
            for (int t = 0; t < 6; t++) {
                const int idx = tid + t * 256;
                const int n = idx >> 3, c4 = (idx & 7) * 4;
                bP[t] = *(const uint4*)&g_wt[n * DD + kc + c4];
            }
        }

#pragma unroll
        for (int ks = 0; ks < 4; ks++) {
            const int k0 = ks * 8;
            uint32_t a[4][4];
#pragma unroll
            for (int mt = 0; mt < 4; mt++) {
                const int base = (wr * 64 + mt * 16 + (lane >> 2)) * AST
                               + k0 + (lane & 3);
                a[mt][0] = __float_as_uint(As[base]);
                a[mt][1] = __float_as_uint(As[base + 8 * AST]);
                a[mt][2] = __float_as_uint(As[base + 4]);
                a[mt][3] = __float_as_uint(As[base + 8 * AST + 4]);
            }
            uint32_t bfr[6][2];
#pragma unroll
            for (int nt = 0; nt < 6; nt++) {
                const int base = (wc * 48 + nt * 8 + (lane >> 2)) * AST
                               + k0 + (lane & 3);
                bfr[nt][0] = __float_as_uint(Bs[base]);
                bfr[nt][1] = __float_as_uint(Bs[base + 4]);
            }
#pragma unroll
            for (int mt = 0; mt < 4; mt++)
#pragma unroll
                for (int nt = 0; nt < 6; nt++)
                    mma_tf32(d[mt][nt], a[mt], bfr[nt]);
        }
        __syncthreads();
    }

#pragma unroll
    for (int nt = 0; nt < 6; nt++) {
        const int cg = wc * 48 + nt * 8;
        const int m  = cg >> 6;
        const int c  = (cg & 63) + (lane & 3) * 2;
        float* gm = (m == 0) ? g_q : (m == 1) ? g_k : g_v;
#pragma unroll
        for (int mt = 0; mt < 4; mt++) {
            const int row = row0 + wr * 64 + mt * 16 + (lane >> 2);
            float2 t0; t0.x = d[mt][nt][0]; t0.y = d[mt][nt][1];
            *(float2*)&gm[(size_t)row * HH + c] = t0;
            float2 t1; t1.x = d[mt][nt][2]; t1.y = d[mt][nt][3];
            *(float2*)&gm[(size_t)(row + 8) * HH + c] = t1;
        }
    }
}

// ===========================================================================
// Kernel 2: tensor-core causal flash attention (tf32 mma.sync), small tiles.
// Q tile 64 x K tile 64. 128 threads = 4 warps; warp w owns rows
// [w*16, w*16+16). smem ~70.7KB -> 3 CTAs/SM (12 warps: cross-CTA overlap
// hides load latency and sync stalls). Blocks pair q-tiles {p, 31-p}:
// exactly 33 key tiles per block; 256 blocks, all resident.
// Fragment banking: Qs/Ks/Ps stride 68 (= 4 mod 32), Vs stride 72
// (= 8 mod 32) -> all mma fragment LDS patterns conflict-free.
// ===========================================================================
#define QST 68
#define KST 68
#define VST 72
#define PST 68

__global__ __launch_bounds__(128, 3) void attn_kernel(float* __restrict__ out)
{
    extern __shared__ float sm[];
    float* Qs = sm;                             // 64*68
    float* Ks = sm + 64 * QST;                  // 64*68
    float* Vs = sm + 64 * (QST + KST);          // 64*72
    float* Ps = sm + 64 * (QST + KST + VST);    // 64*68

    const int tid  = threadIdx.x;
    const int w    = tid >> 5;
    const int lane = tid & 31;
    const int qr   = lane >> 2;
    const int ql   = lane & 3;
    const int b    = blockIdx.y;
    const int pair = blockIdx.x;

#pragma unroll 1
    for (int half = 0; half < 2; half++) {
        const int qt = half ? (31 - pair) : pair;
        const int q0 = qt * 64;

        // ---- load Q tile (scaled, tf32) ----
        {
            const float* qp = g_q + ((size_t)b * TT + q0) * HH;
#pragma unroll
            for (int t = 0; t < 8; t++) {
                const int idx = tid + t * 128;      // 1024 float4 slots
                const int r  = idx >> 4;
                const int c4 = (idx & 15) << 2;
                float4 v = *(const float4*)&qp[r * HH + c4];
                uint4 u;
                u.x = f32_to_tf32(v.x * 0.125f); u.y = f32_to_tf32(v.y * 0.125f);
                u.z = f32_to_tf32(v.z * 0.125f); u.w = f32_to_tf32(v.w * 0.125f);
                *(uint4*)&Qs[r * QST + c4] = u;
            }
        }

        float o[8][4];
        float m0 = -1e30f, m1 = -1e30f, l0 = 0.f, l1 = 0.f;
#pragma unroll
        for (int nt = 0; nt < 8; nt++)
#pragma unroll
            for (int r = 0; r < 4; r++) o[nt][r] = 0.f;
        __syncthreads();

#pragma unroll 1
        for (int kt = 0; kt <= qt; kt++) {
            const float* kp = g_k + ((size_t)b * TT + kt * 64) * HH;
            const float* vp = g_v + ((size_t)b * TT + kt * 64) * HH;

            // ---- load K, V tiles (tf32) ----
#pragma unroll
            for (int t = 0; t < 8; t++) {
                const int idx = tid + t * 128;
                const int r  = idx >> 4;
                const int c4 = (idx & 15) << 2;
                float4 kv = *(const float4*)&kp[r * HH + c4];
                uint4 uk;
                uk.x = f32_to_tf32(kv.x); uk.y = f32_to_tf32(kv.y);
                uk.z = f32_to_tf32(kv.z); uk.w = f32_to_tf32(kv.w);
                *(uint4*)&Ks[r * KST + c4] = uk;
                float4 vv = *(const float4*)&vp[r * HH + c4];
                uint4 uv;
                uv.x = f32_to_tf32(vv.x); uv.y = f32_to_tf32(vv.y);
                uv.z = f32_to_tf32(vv.z); uv.w = f32_to_tf32(vv.w);
                *(uint4*)&Vs[r * VST + c4] = uv;
            }
            __syncthreads();

            // ---- S = Q K^T : 8 n-tiles x 8 k-steps ----
            float s[8][4];
#pragma unroll
            for (int nt = 0; nt < 8; nt++)
#pragma unroll
                for (int r = 0; r < 4; r++) s[nt][r] = 0.f;

#pragma unroll
            for (int ks = 0; ks < 8; ks++) {
                const int k0 = ks * 8;
                uint32_t a[4];
                {
                    const int base = (w * 16 + qr) * QST + k0 + ql;
                    a[0] = __float_as_uint(Qs[base]);
                    a[1] = __float_as_uint(Qs[base + 8 * QST]);
                    a[2] = __float_as_uint(Qs[base + 4]);
                    a[3] = __float_as_uint(Qs[base + 8 * QST + 4]);
                }
#pragma unroll
                for (int nt = 0; nt < 8; nt++) {
                    uint32_t bf[2];
                    const int base = (nt * 8 + qr) * KST + k0 + ql;
                    bf[0] = __float_as_uint(Ks[base]);
                    bf[1] = __float_as_uint(Ks[base + 4]);
                    mma_tf32(s[nt], a, bf);
                }
            }

            // ---- causal mask (diagonal tile) ----
            if (kt == qt) {
                const int r0 = w * 16 + qr;
#pragma unroll
                for (int nt = 0; nt < 8; nt++) {
                    const int c = nt * 8 + 2 * ql;
                    if (c     > r0)     s[nt][0] = -1e30f;
                    if (c + 1 > r0)     s[nt][1] = -1e30f;
                    if (c     > r0 + 8) s[nt][2] = -1e30f;
                    if (c + 1 > r0 + 8) s[nt][3] = -1e30f;
                }
            }

            // ---- online softmax on accumulator layout ----
            {
                float mx0 = -1e30f, mx1 = -1e30f;
#pragma unroll
                for (int nt = 0; nt < 8; nt++) {
                    mx0 = fmaxf(mx0, fmaxf(s[nt][0], s[nt][1]));
                    mx1 = fmaxf(mx1, fmaxf(s[nt][2], s[nt][3]));
                }
                mx0 = fmaxf(mx0, __shfl_xor_sync(0xffffffffu, mx0, 1));
                mx0 = fmaxf(mx0, __shfl_xor_sync(0xffffffffu, mx0, 2));
                mx1 = fmaxf(mx1, __shfl_xor_sync(0xffffffffu, mx1, 1));
                mx1 = fmaxf(mx1, __shfl_xor_sync(0xffffffffu, mx1, 2));
                mx0 = fmaxf(mx0, m0);
                mx1 = fmaxf(mx1, m1);

                const float alpha0 = __expf(m0 - mx0);
                const float alpha1 = __expf(m1 - mx1);
                m0 = mx0; m1 = mx1;

                float rs0 = 0.f, rs1 = 0.f;
#pragma unroll
                for (int nt = 0; nt < 8; nt++) {
                    s[nt][0] = __expf(s[nt][0] - mx0);
                    s[nt][1] = __expf(s[nt][1] - mx0);
                    s[nt][2] = __expf(s[nt][2] - mx1);
                    s[nt][3] = __expf(s[nt][3] - mx1);
                    rs0 += s[nt][0] + s[nt][1];
                    rs1 += s[nt][2] + s[nt][3];
                }
                rs0 += __shfl_xor_sync(0xffffffffu, rs0, 1);
                rs0 += __shfl_xor_sync(0xffffffffu, rs0, 2);
                rs1 += __shfl_xor_sync(0xffffffffu, rs1, 1);
                rs1 += __shfl_xor_sync(0xffffffffu, rs1, 2);
                l0 = l0 * alpha0 + rs0;
                l1 = l1 * alpha1 + rs1;

#pragma unroll
                for (int nt = 0; nt < 8; nt++) {
                    o[nt][0] *= alpha0; o[nt][1] *= alpha0;
                    o[nt][2] *= alpha1; o[nt][3] *= alpha1;
                }

                // store P (warp-private rows: no block sync needed)
                const int r0 = w * 16 + qr;
#pragma unroll
                for (int nt = 0; nt < 8; nt++) {
                    float2 t0; t0.x = s[nt][0]; t0.y = s[nt][1];
                    *(float2*)&Ps[r0 * PST + nt * 8 + 2 * ql] = t0;
                    float2 t1; t1.x = s[nt][2]; t1.y = s[nt][3];
                    *(float2*)&Ps[(r0 + 8) * PST + nt * 8 + 2 * ql] = t1;
                }
            }

            // ---- O += P V : 8 n-tiles x 8 k-steps ----
#pragma unroll
            for (int ks = 0; ks < 8; ks++) {
                const int k0 = ks * 8;
                uint32_t a[4];
                {
                    const int base = (w * 16 + qr) * PST + k0 + ql;
                    a[0] = __float_as_uint(Ps[base]);
                    a[1] = __float_as_uint(Ps[base + 8 * PST]);
                    a[2] = __float_as_uint(Ps[base + 4]);
                    a[3] = __float_as_uint(Ps[base + 8 * PST + 4]);
                }
#pragma unroll
                for (int nt = 0; nt < 8; nt++) {
                    uint32_t bf[2];
                    const int base = (k0 + ql) * VST + nt * 8 + qr;
                    bf[0] = __float_as_uint(Vs[base]);
                    bf[1] = __float_as_uint(Vs[base + 4 * VST]);
                    mma_tf32(o[nt], a, bf);
                }
            }
            __syncthreads();
        }

        // ---- epilogue ----
        {
            const float inv0 = 1.f / l0;
            const float inv1 = 1.f / l1;
            const int row = q0 + w * 16 + qr;
#pragma unroll
            for (int nt = 0; nt < 8; nt++) {
                const int c = nt * 8 + 2 * ql;
                float2 t0; t0.x = o[nt][0] * inv0; t0.y = o[nt][1] * inv0;
                *(float2*)&out[((size_t)b * TT + row) * HH + c] = t0;
                float2 t1; t1.x = o[nt][2] * inv1; t1.y = o[nt][3] * inv1;
                *(float2*)&out[((size_t)b * TT + row + 8) * HH + c] = t1;
            }
        }
        __syncthreads();
    }
}

// ===========================================================================
extern "C" void kernel_launch(void* const* d_in, const int* in_sizes, int n_in,
                              void* d_out, int out_size)
{
    (void)in_sizes; (void)n_in; (void)out_size;
    const float* x  = (const float*)d_in[0];
    const float* Wq = (const float*)d_in[1];
    const float* Wk = (const float*)d_in[2];
    const float* Wv = (const float*)d_in[3];
    float* out = (float*)d_out;

    wt_kernel<<<(3 * HH * DD) / 256, 256>>>(Wq, Wk, Wv);

    proj_mma_kernel<<<(BB * TT) / 128, 256>>>(x);

    const int attn_smem = 64 * (QST + KST + VST + PST) * 4;   // 70,656 B
    cudaFuncSetAttribute(attn_kernel,
                         cudaFuncAttributeMaxDynamicSharedMemorySize, attn_smem);
    dim3 g(16, BB);
    attn_kernel<<<g, 128, attn_smem>>>(out);
}